// round 12
// baseline (speedup 1.0000x reference)
#include <cuda_runtime.h>
#include <cuda_bf16.h>
#include <math.h>
#include <stdint.h>

#define BB 32
#define TT 512
#define II 1024
#define HH 1024
#define GG 4096   // 4*H

// ---- scratch (static __device__ arrays; no allocation allowed) ----
__device__ float g_xproj[67108864];            // [T][B][4H] (256 MB)
__device__ __nv_bfloat16 g_hhi[2][BB * HH];    // bf16-split hidden ping-pong
__device__ __nv_bfloat16 g_hlo[2][BB * HH];
__device__ float g_c[BB * HH];
__device__ unsigned g_bar_cnt;
__device__ volatile unsigned g_bar_gen;
// bf16 hi/lo split operands for tensor-core xproj
__device__ __nv_bfloat16 g_xhi[TT * BB * II];  // [r=t*32+b][i]
__device__ __nv_bfloat16 g_xlo[TT * BB * II];
__device__ __nv_bfloat16 g_whi[GG * II];       // [n][k]
__device__ __nv_bfloat16 g_wlo[GG * II];

__device__ __forceinline__ float sigmoidf_(float x) {
    return 1.0f / (1.0f + __expf(-x));
}

__device__ __forceinline__ uint32_t smem_u32(const void* p) {
    uint32_t a;
    asm("{ .reg .u64 t; cvta.to.shared.u64 t, %1; cvt.u32.u64 %0, t; }"
        : "=r"(a) : "l"(p));
    return a;
}

// ldmatrix x4 (sm_75+)
__device__ __forceinline__ void ldsm4(uint32_t* r, uint32_t addr) {
    asm volatile("ldmatrix.sync.aligned.m8n8.x4.shared.b16 {%0,%1,%2,%3}, [%4];"
                 : "=r"(r[0]), "=r"(r[1]), "=r"(r[2]), "=r"(r[3]) : "r"(addr));
}
// mma.sync bf16 (sm_80+)
__device__ __forceinline__ void mma16816(float* c, const uint32_t* a,
                                         uint32_t b0, uint32_t b1) {
    asm volatile(
        "mma.sync.aligned.m16n8k16.row.col.f32.bf16.bf16.f32 "
        "{%0,%1,%2,%3}, {%4,%5,%6,%7}, {%8,%9}, {%0,%1,%2,%3};"
        : "+f"(c[0]), "+f"(c[1]), "+f"(c[2]), "+f"(c[3])
        : "r"(a[0]), "r"(a[1]), "r"(a[2]), "r"(a[3]), "r"(b0), "r"(b1));
}

// split a float into bf16 hi + bf16 lo
__device__ __forceinline__ void split1(float v, __nv_bfloat16& h, __nv_bfloat16& l) {
    h = __float2bfloat16(v);
    l = __float2bfloat16(v - __bfloat162float(h));
}

// ---------------------------------------------------------------------------
// init: c state, bf16-split h0, barrier reset
// ---------------------------------------------------------------------------
__global__ void init_kernel(const float* __restrict__ h0, const float* __restrict__ c0) {
    int i = blockIdx.x * blockDim.x + threadIdx.x;
    if (i < BB * HH) {
        g_c[i] = c0[i];
        __nv_bfloat16 hi, lo;
        split1(h0[i], hi, lo);
        g_hhi[0][i] = hi;
        g_hlo[0][i] = lo;
    }
    if (i == 0) { g_bar_cnt = 0; g_bar_gen = 0; }
}

__device__ __forceinline__ void split4(float4 v, __nv_bfloat16* hi, __nv_bfloat16* lo,
                                       size_t r) {
    float vv[4] = {v.x, v.y, v.z, v.w};
    __nv_bfloat16 h[4], l[4];
#pragma unroll
    for (int j = 0; j < 4; j++) split1(vv[j], h[j], l[j]);
    *(__nv_bfloat162*)(hi + r)     = __halves2bfloat162(h[0], h[1]);
    *(__nv_bfloat162*)(hi + r + 2) = __halves2bfloat162(h[2], h[3]);
    *(__nv_bfloat162*)(lo + r)     = __halves2bfloat162(l[0], l[1]);
    *(__nv_bfloat162*)(lo + r + 2) = __halves2bfloat162(l[2], l[3]);
}

__global__ void conv_x_kernel(const float* __restrict__ x) {
    int64_t n4 = (int64_t)TT * BB * II / 4;
    for (int64_t q = blockIdx.x * blockDim.x + threadIdx.x; q < n4;
         q += (int64_t)gridDim.x * blockDim.x) {
        int64_t i4 = q * 4;
        int i  = (int)(i4 & (II - 1));
        int bt = (int)(i4 >> 10);
        int t  = bt & (TT - 1);
        int b  = bt >> 9;
        float4 v = *(const float4*)(x + i4);
        size_t r = ((size_t)t * BB + b) * II + i;
        split4(v, g_xhi, g_xlo, r);
    }
}

__global__ void conv_w_kernel(const float* __restrict__ Wi) {
    int64_t n4 = (int64_t)GG * II / 4;
    for (int64_t q = blockIdx.x * blockDim.x + threadIdx.x; q < n4;
         q += (int64_t)gridDim.x * blockDim.x) {
        float4 v = *(const float4*)(Wi + q * 4);
        split4(v, g_whi, g_wlo, (size_t)q * 4);
    }
}

// ---------------------------------------------------------------------------
// xproj GEMM via mma.sync bf16 (validated R8 version, unchanged).
// ---------------------------------------------------------------------------
#define LDP 72
#define XP_SMEM (4 * 128 * LDP * 2)

__global__ __launch_bounds__(256, 2) void xproj_mma_kernel(
    const float* __restrict__ bi, const float* __restrict__ bh,
    float* __restrict__ outbuf)
{
    extern __shared__ char smem[];
    __nv_bfloat16* Ah = (__nv_bfloat16*)smem;
    __nv_bfloat16* Al = Ah + 128 * LDP;
    __nv_bfloat16* Bh = Al + 128 * LDP;
    __nv_bfloat16* Bl = Bh + 128 * LDP;

    const int tid  = threadIdx.x;
    const int w    = tid >> 5;
    const int lane = tid & 31;
    const int ntile = blockIdx.x;
    const int mtile = blockIdx.y;
    const int wm = (w >> 1) * 32;
    const int wn = (w & 1) * 64;

    const __nv_bfloat16* gAh = g_xhi + (size_t)(mtile * 128) * II;
    const __nv_bfloat16* gAl = g_xlo + (size_t)(mtile * 128) * II;
    const __nv_bfloat16* gBh = g_whi + (size_t)(ntile * 128) * II;
    const __nv_bfloat16* gBl = g_wlo + (size_t)(ntile * 128) * II;

    float acc[2][8][4];
#pragma unroll
    for (int mi = 0; mi < 2; mi++)
#pragma unroll
        for (int nj = 0; nj < 8; nj++)
#pragma unroll
            for (int q = 0; q < 4; q++) acc[mi][nj][q] = 0.f;

    const int a_row = lane & 15;
    const int a_col = (lane >> 4) << 3;
    const int b_row = ((lane >> 4) << 3) + (lane & 7);
    const int b_col = ((lane >> 3) & 1) << 3;

    for (int chunk = 0; chunk < 16; chunk++) {
        const int k0 = chunk * 64;
#pragma unroll
        for (int it = 0; it < 4; it++) {
            int idx = tid + it * 256;
            int row = idx >> 3;
            int cg  = idx & 7;
            size_t g = (size_t)row * II + k0 + cg * 8;
            int s = row * LDP + cg * 8;
            *(uint4*)(Ah + s) = *(const uint4*)(gAh + g);
            *(uint4*)(Al + s) = *(const uint4*)(gAl + g);
            *(uint4*)(Bh + s) = *(const uint4*)(gBh + g);
            *(uint4*)(Bl + s) = *(const uint4*)(gBl + g);
        }
        __syncthreads();

#pragma unroll
        for (int kk = 0; kk < 4; kk++) {
            const int ks = kk * 16;
            uint32_t ah[2][4], al[2][4];
#pragma unroll
            for (int mi = 0; mi < 2; mi++) {
                ldsm4(ah[mi], smem_u32(Ah + (wm + mi * 16 + a_row) * LDP + ks + a_col));
                ldsm4(al[mi], smem_u32(Al + (wm + mi * 16 + a_row) * LDP + ks + a_col));
            }
#pragma unroll
            for (int g2 = 0; g2 < 4; g2++) {
                uint32_t bh4[4], bl4[4];
                ldsm4(bh4, smem_u32(Bh + (wn + g2 * 16 + b_row) * LDP + ks + b_col));
                ldsm4(bl4, smem_u32(Bl + (wn + g2 * 16 + b_row) * LDP + ks + b_col));
#pragma unroll
                for (int mi = 0; mi < 2; mi++) {
                    mma16816(acc[mi][g2 * 2],     ah[mi], bh4[0], bh4[1]);
                    mma16816(acc[mi][g2 * 2],     ah[mi], bl4[0], bl4[1]);
                    mma16816(acc[mi][g2 * 2],     al[mi], bh4[0], bh4[1]);
                    mma16816(acc[mi][g2 * 2 + 1], ah[mi], bh4[2], bh4[3]);
                    mma16816(acc[mi][g2 * 2 + 1], ah[mi], bl4[2], bl4[3]);
                    mma16816(acc[mi][g2 * 2 + 1], al[mi], bh4[2], bh4[3]);
                }
            }
        }
        __syncthreads();
    }

    const int colw = ntile * 128 + wn;
#pragma unroll
    for (int mi = 0; mi < 2; mi++) {
        int r0 = mtile * 128 + wm + mi * 16 + (lane >> 2);
#pragma unroll
        for (int nj = 0; nj < 8; nj++) {
            int c = colw + nj * 8 + (lane & 3) * 2;
            float b0 = bi[c] + bh[c];
            float b1 = bi[c + 1] + bh[c + 1];
            *(float2*)(outbuf + (size_t)r0 * GG + c) =
                make_float2(acc[mi][nj][0] + b0, acc[mi][nj][1] + b1);
            *(float2*)(outbuf + (size_t)(r0 + 8) * GG + c) =
                make_float2(acc[mi][nj][2] + b0, acc[mi][nj][3] + b1);
        }
    }
}

// ---------------------------------------------------------------------------
// Persistent tensor-core recurrence (v3): 512 threads, 16 warps.
// Block bx owns 8 h-columns (32 gate cols). Warp w = mt*8 + kq:
// mt = m-tile (16 batch rows), kq = K eighth (128). 4 warps per SMSP to hide
// LDG/LDSM latency behind HMMA. Fixed-order 7-partial reduction -> kq0 warps
// apply activations in registers. One grid barrier per step.
// ---------------------------------------------------------------------------
#define LDKW 1032                        // padded row stride (bf16): 2064 B
#define RC_WH   (32 * LDKW * 2)          // one Wh buffer bytes (66048)
#define RC_RED  (14 * 32 * 16 * 4)       // 28672 B
#define RC_SMEM (2 * RC_WH + RC_RED)     // 160768 B

__device__ __forceinline__ void grid_sync(unsigned& gen) {
    __syncthreads();
    if (threadIdx.x == 0) {
        __threadfence();
        unsigned arrived = atomicAdd(&g_bar_cnt, 1u);
        if (arrived == gridDim.x - 1) {
            g_bar_cnt = 0;
            __threadfence();
            g_bar_gen = gen + 1;
        } else {
            while (g_bar_gen <= gen) { }
            __threadfence();
        }
    }
    gen++;
    __syncthreads();
}

__global__ __launch_bounds__(512, 1) void lstm_persist_tc(
    const float* __restrict__ Wh, float* __restrict__ out)
{
    extern __shared__ char smem_raw[];
    __nv_bfloat16* WhHi = (__nv_bfloat16*)smem_raw;                 // [32][LDKW]
    __nv_bfloat16* WhLo = WhHi + 32 * LDKW;
    float* red = (float*)(smem_raw + 2 * RC_WH);                    // [14][32][16]

    const int bx    = blockIdx.x;
    const int tid   = threadIdx.x;
    const int w     = tid >> 5;
    const int lane  = tid & 31;
    const int mt    = w >> 3;        // 0..1 (m-tile of 16)
    const int kq    = w & 7;         // 0..7 (K eighth)
    const int hbase = bx * 8;

    // ---- one-time: load + split Wh slice into SMEM ----
    {
        const int n  = tid >> 4;         // 0..31
        const int cq = tid & 15;         // k chunk of 64
        const int grow = (n >> 3) * HH + hbase + (n & 7);
        const float* src = Wh + (size_t)grow * HH;
#pragma unroll 4
        for (int kk = 0; kk < 8; kk++) {
            int k = cq * 64 + kk * 8;
            float4 va = *(const float4*)(src + k);
            float4 vb = *(const float4*)(src + k + 4);
            float vv[8] = {va.x, va.y, va.z, va.w, vb.x, vb.y, vb.z, vb.w};
            __nv_bfloat16 h[8], l[8];
#pragma unroll
            for (int j = 0; j < 8; j++) split1(vv[j], h[j], l[j]);
            __nv_bfloat162* dh = (__nv_bfloat162*)(WhHi + n * LDKW + k);
            __nv_bfloat162* dl = (__nv_bfloat162*)(WhLo + n * LDKW + k);
#pragma unroll
            for (int j = 0; j < 4; j++) {
                dh[j] = __halves2bfloat162(h[2 * j], h[2 * j + 1]);
                dl[j] = __halves2bfloat162(l[2 * j], l[2 * j + 1]);
            }
        }
    }
    __syncthreads();

    const int b_row = ((lane >> 4) << 3) + (lane & 7);
    const int b_col = ((lane >> 3) & 1) << 3;
    const uint32_t bhi0_base = smem_u32(WhHi + b_row * LDKW + b_col);
    const uint32_t bhi1_base = smem_u32(WhHi + (16 + b_row) * LDKW + b_col);
    const uint32_t blo0_base = smem_u32(WhLo + b_row * LDKW + b_col);
    const uint32_t blo1_base = smem_u32(WhLo + (16 + b_row) * LDKW + b_col);

    // m16n8k16 lane map components
    const int ar0 = mt * 16 + (lane >> 2);       // batch rows ar0 and ar0+8
    const int ak  = (lane & 3) * 2;
    const int r0  = mt * 16 + (lane >> 2);       // output row (kq0 role)
    const int c0  = (lane & 3) * 2;              // output local col pair

    unsigned gen = 0;

    for (int t = 0; t < TT; t++) {
        const uint32_t* hhi = (const uint32_t*)g_hhi[t & 1];
        const uint32_t* hlo = (const uint32_t*)g_hlo[t & 1];

        // ---- prefetch x_proj[t] gates + c (kq0 items) — overlaps K loop ----
        float xpr[4][4], cpr[4];
        if (kq == 0) {
            const float* xb = g_xproj + (size_t)t * BB * GG;
#pragma unroll
            for (int q = 0; q < 4; q++) {
                int b  = r0 + (q >> 1) * 8;
                int cc = c0 + (q & 1);
                const float* p = xb + (size_t)b * GG + hbase + cc;
                xpr[0][q] = p[0];
                xpr[1][q] = p[HH];
                xpr[2][q] = p[2 * HH];
                xpr[3][q] = p[3 * HH];
                cpr[q] = g_c[b * HH + hbase + cc];
            }
        }

        float acc[4][4];
#pragma unroll
        for (int f = 0; f < 4; f++)
#pragma unroll
            for (int q = 0; q < 4; q++) acc[f][q] = 0.f;

        // ---- K loop: this warp's eighth (128 K) ----
#pragma unroll
        for (int it = 0; it < 8; it++) {
            const int k = kq * 128 + it * 16;
            uint32_t ah[4], al[4];
            const int i00 = (ar0 * HH + k + ak) >> 1;
            const int i10 = ((ar0 + 8) * HH + k + ak) >> 1;
            ah[0] = hhi[i00];     ah[1] = hhi[i10];
            ah[2] = hhi[i00 + 4]; ah[3] = hhi[i10 + 4];
            al[0] = hlo[i00];     al[1] = hlo[i10];
            al[2] = hlo[i00 + 4]; al[3] = hlo[i10 + 4];

            uint32_t bh0[4], bh1[4], bl0[4], bl1[4];
            ldsm4(bh0, bhi0_base + k * 2);
            ldsm4(bh1, bhi1_base + k * 2);
            ldsm4(bl0, blo0_base + k * 2);
            ldsm4(bl1, blo1_base + k * 2);

            mma16816(acc[0], ah, bh0[0], bh0[1]);
            mma16816(acc[1], ah, bh0[2], bh0[3]);
            mma16816(acc[2], ah, bh1[0], bh1[1]);
            mma16816(acc[3], ah, bh1[2], bh1[3]);
            mma16816(acc[0], ah, bl0[0], bl0[1]);
            mma16816(acc[1], ah, bl0[2], bl0[3]);
            mma16816(acc[2], ah, bl1[0], bl1[1]);
            mma16816(acc[3], ah, bl1[2], bl1[3]);
            mma16816(acc[0], al, bh0[0], bh0[1]);
            mma16816(acc[1], al, bh0[2], bh0[3]);
            mma16816(acc[2], al, bh1[0], bh1[1]);
            mma16816(acc[3], al, bh1[2], bh1[3]);
        }

        // ---- cross-warp K reduction (fixed order -> deterministic) ----
        if (kq != 0) {
            float* rdst = red + ((mt * 7 + (kq - 1)) * 32 + lane) * 16;
#pragma unroll
            for (int f = 0; f < 4; f++)
#pragma unroll
                for (int q = 0; q < 4; q++) rdst[f * 4 + q] = acc[f][q];
        }
        __syncthreads();

        if (kq == 0) {
#pragma unroll
            for (int p = 0; p < 7; p++) {
                const float* rsrc = red + ((mt * 7 + p) * 32 + lane) * 16;
#pragma unroll
                for (int f = 0; f < 4; f++)
#pragma unroll
                    for (int q = 0; q < 4; q++) acc[f][q] += rsrc[f * 4 + q];
            }

            // ---- activations entirely in registers ----
            __nv_bfloat16* hhi_n = g_hhi[(t + 1) & 1];
            __nv_bfloat16* hlo_n = g_hlo[(t + 1) & 1];
#pragma unroll
            for (int half = 0; half < 2; half++) {
                const int b = r0 + half * 8;
                float hn[2], cn[2];
#pragma unroll
                for (int j = 0; j < 2; j++) {
                    const int q = half * 2 + j;
                    float ig = sigmoidf_(acc[0][q] + xpr[0][q]);
                    float fg = sigmoidf_(acc[1][q] + xpr[1][q]);
                    float gg = tanhf(acc[2][q] + xpr[2][q]);
                    float og = sigmoidf_(acc[3][q] + xpr[3][q]);
                    cn[j] = fmaf(fg, cpr[q], ig * gg);
                    hn[j] = og * tanhf(cn[j]);
                }
                const int idx = b * HH + hbase + c0;
                *(float2*)(g_c + idx) = make_float2(cn[0], cn[1]);
                __nv_bfloat16 h0h, h0l, h1h, h1l;
                split1(hn[0], h0h, h0l);
                split1(hn[1], h1h, h1l);
                *(__nv_bfloat162*)(hhi_n + idx) = __halves2bfloat162(h0h, h1h);
                *(__nv_bfloat162*)(hlo_n + idx) = __halves2bfloat162(h0l, h1l);
                *(float2*)(out + (size_t)b * TT * HH + (size_t)t * HH + hbase + c0) =
                    make_float2(hn[0], hn[1]);
            }
        }

        grid_sync(gen);   // h fully published before next step reads it
    }
}

// ---------------------------------------------------------------------------
// tail: h_T (= output[:, T-1, :]) and c_T appended after output [B,T,H]
// ---------------------------------------------------------------------------
__global__ void finish_kernel(float* __restrict__ out) {
    int i = blockIdx.x * blockDim.x + threadIdx.x;
    if (i < BB * HH) {
        int b = i >> 10, hc = i & (HH - 1);
        out[(size_t)BB * TT * HH + i] =
            out[(size_t)b * TT * HH + (size_t)(TT - 1) * HH + hc];
        out[(size_t)BB * TT * HH + BB * HH + i] = g_c[i];
    }
}

extern "C" void kernel_launch(void* const* d_in, const int* in_sizes, int n_in,
                              void* d_out, int out_size) {
    const float* x  = (const float*)d_in[0];
    const float* h0 = (const float*)d_in[1];
    const float* c0 = (const float*)d_in[2];
    const float* Wi = (const float*)d_in[3];
    const float* bi = (const float*)d_in[4];
    const float* Wh = (const float*)d_in[5];
    const float* bh = (const float*)d_in[6];
    float* out = (float*)d_out;

    cudaFuncSetAttribute(xproj_mma_kernel, cudaFuncAttributeMaxDynamicSharedMemorySize,
                         XP_SMEM);
    cudaFuncSetAttribute(lstm_persist_tc, cudaFuncAttributeMaxDynamicSharedMemorySize,
                         RC_SMEM);

    init_kernel<<<(BB * HH + 255) / 256, 256>>>(h0, c0);
    conv_x_kernel<<<4096, 256>>>(x);
    conv_w_kernel<<<1024, 256>>>(Wi);

    float* xproj_ptr;
    cudaGetSymbolAddress((void**)&xproj_ptr, g_xproj);
    xproj_mma_kernel<<<dim3(32, 128), 256, XP_SMEM>>>(bi, bh, xproj_ptr);

    lstm_persist_tc<<<128, 512, RC_SMEM>>>(Wh, out);
    finish_kernel<<<(BB * HH + 255) / 256, 256>>>(out);
}

// round 15
// speedup vs baseline: 1.2001x; 1.2001x over previous
#include <cuda_runtime.h>
#include <cuda_bf16.h>
#include <math.h>
#include <stdint.h>

#define BB 32
#define TT 512
#define II 1024
#define HH 1024
#define GG 4096   // 4*H

// ---- scratch (static __device__ arrays; no allocation allowed) ----
__device__ float g_xproj[67108864];            // [T][B][4H] (256 MB)
// packed hidden state: per hcol-pair, low u32 = bf16 hi-pair, high u32 = bf16 lo-pair
__device__ unsigned long long g_hpk[2][BB * HH / 2];
__device__ float g_c[BB * HH];
__device__ unsigned g_bar_cnt;
__device__ volatile unsigned g_bar_gen;
// bf16 hi/lo split operands for tensor-core xproj
__device__ __nv_bfloat16 g_xhi[TT * BB * II];  // [r=t*32+b][i]
__device__ __nv_bfloat16 g_xlo[TT * BB * II];
__device__ __nv_bfloat16 g_whi[GG * II];       // [n][k]
__device__ __nv_bfloat16 g_wlo[GG * II];

__device__ __forceinline__ float sigmoidf_(float x) {
    return 1.0f / (1.0f + __expf(-x));
}

__device__ __forceinline__ uint32_t smem_u32(const void* p) {
    uint32_t a;
    asm("{ .reg .u64 t; cvta.to.shared.u64 t, %1; cvt.u32.u64 %0, t; }"
        : "=r"(a) : "l"(p));
    return a;
}

// ldmatrix x4 (sm_75+)
__device__ __forceinline__ void ldsm4(uint32_t* r, uint32_t addr) {
    asm volatile("ldmatrix.sync.aligned.m8n8.x4.shared.b16 {%0,%1,%2,%3}, [%4];"
                 : "=r"(r[0]), "=r"(r[1]), "=r"(r[2]), "=r"(r[3]) : "r"(addr));
}
// mma.sync bf16 (sm_80+)
__device__ __forceinline__ void mma16816(float* c, const uint32_t* a,
                                         uint32_t b0, uint32_t b1) {
    asm volatile(
        "mma.sync.aligned.m16n8k16.row.col.f32.bf16.bf16.f32 "
        "{%0,%1,%2,%3}, {%4,%5,%6,%7}, {%8,%9}, {%0,%1,%2,%3};"
        : "+f"(c[0]), "+f"(c[1]), "+f"(c[2]), "+f"(c[3])
        : "r"(a[0]), "r"(a[1]), "r"(a[2]), "r"(a[3]), "r"(b0), "r"(b1));
}

// split a float into bf16 hi + bf16 lo
__device__ __forceinline__ void split1(float v, __nv_bfloat16& h, __nv_bfloat16& l) {
    h = __float2bfloat16(v);
    l = __float2bfloat16(v - __bfloat162float(h));
}

__device__ __forceinline__ uint32_t bf2_u32(__nv_bfloat16 a, __nv_bfloat16 b) {
    __nv_bfloat162 p = __halves2bfloat162(a, b);
    return *(uint32_t*)&p;
}

// pack two adjacent-hcol h values into one u64 (hi-pair low, lo-pair high)
__device__ __forceinline__ unsigned long long pack_h2(float v0, float v1) {
    __nv_bfloat16 h0, l0, h1, l1;
    split1(v0, h0, l0);
    split1(v1, h1, l1);
    return (unsigned long long)bf2_u32(h0, h1) |
           ((unsigned long long)bf2_u32(l0, l1) << 32);
}

// ---------------------------------------------------------------------------
// init: c state, packed-split h0, barrier reset
// ---------------------------------------------------------------------------
__global__ void init_kernel(const float* __restrict__ h0, const float* __restrict__ c0) {
    int i = blockIdx.x * blockDim.x + threadIdx.x;
    if (i < BB * HH) g_c[i] = c0[i];
    if (i < BB * HH / 2)
        g_hpk[0][i] = pack_h2(h0[2 * i], h0[2 * i + 1]);
    if (i == 0) { g_bar_cnt = 0; g_bar_gen = 0; }
}

__device__ __forceinline__ void split4(float4 v, __nv_bfloat16* hi, __nv_bfloat16* lo,
                                       size_t r) {
    float vv[4] = {v.x, v.y, v.z, v.w};
    __nv_bfloat16 h[4], l[4];
#pragma unroll
    for (int j = 0; j < 4; j++) split1(vv[j], h[j], l[j]);
    *(__nv_bfloat162*)(hi + r)     = __halves2bfloat162(h[0], h[1]);
    *(__nv_bfloat162*)(hi + r + 2) = __halves2bfloat162(h[2], h[3]);
    *(__nv_bfloat162*)(lo + r)     = __halves2bfloat162(l[0], l[1]);
    *(__nv_bfloat162*)(lo + r + 2) = __halves2bfloat162(l[2], l[3]);
}

__global__ void conv_x_kernel(const float* __restrict__ x) {
    int64_t n4 = (int64_t)TT * BB * II / 4;
    for (int64_t q = blockIdx.x * blockDim.x + threadIdx.x; q < n4;
         q += (int64_t)gridDim.x * blockDim.x) {
        int64_t i4 = q * 4;
        int i  = (int)(i4 & (II - 1));
        int bt = (int)(i4 >> 10);
        int t  = bt & (TT - 1);
        int b  = bt >> 9;
        float4 v = *(const float4*)(x + i4);
        size_t r = ((size_t)t * BB + b) * II + i;
        split4(v, g_xhi, g_xlo, r);
    }
}

__global__ void conv_w_kernel(const float* __restrict__ Wi) {
    int64_t n4 = (int64_t)GG * II / 4;
    for (int64_t q = blockIdx.x * blockDim.x + threadIdx.x; q < n4;
         q += (int64_t)gridDim.x * blockDim.x) {
        float4 v = *(const float4*)(Wi + q * 4);
        split4(v, g_whi, g_wlo, (size_t)q * 4);
    }
}

// ---------------------------------------------------------------------------
// xproj GEMM via mma.sync bf16 (validated R8 version, unchanged).
// ---------------------------------------------------------------------------
#define LDP 72
#define XP_SMEM (4 * 128 * LDP * 2)

__global__ __launch_bounds__(256, 2) void xproj_mma_kernel(
    const float* __restrict__ bi, const float* __restrict__ bh,
    float* __restrict__ outbuf)
{
    extern __shared__ char smem[];
    __nv_bfloat16* Ah = (__nv_bfloat16*)smem;
    __nv_bfloat16* Al = Ah + 128 * LDP;
    __nv_bfloat16* Bh = Al + 128 * LDP;
    __nv_bfloat16* Bl = Bh + 128 * LDP;

    const int tid  = threadIdx.x;
    const int w    = tid >> 5;
    const int lane = tid & 31;
    const int ntile = blockIdx.x;
    const int mtile = blockIdx.y;
    const int wm = (w >> 1) * 32;
    const int wn = (w & 1) * 64;

    const __nv_bfloat16* gAh = g_xhi + (size_t)(mtile * 128) * II;
    const __nv_bfloat16* gAl = g_xlo + (size_t)(mtile * 128) * II;
    const __nv_bfloat16* gBh = g_whi + (size_t)(ntile * 128) * II;
    const __nv_bfloat16* gBl = g_wlo + (size_t)(ntile * 128) * II;

    float acc[2][8][4];
#pragma unroll
    for (int mi = 0; mi < 2; mi++)
#pragma unroll
        for (int nj = 0; nj < 8; nj++)
#pragma unroll
            for (int q = 0; q < 4; q++) acc[mi][nj][q] = 0.f;

    const int a_row = lane & 15;
    const int a_col = (lane >> 4) << 3;
    const int b_row = ((lane >> 4) << 3) + (lane & 7);
    const int b_col = ((lane >> 3) & 1) << 3;

    for (int chunk = 0; chunk < 16; chunk++) {
        const int k0 = chunk * 64;
#pragma unroll
        for (int it = 0; it < 4; it++) {
            int idx = tid + it * 256;
            int row = idx >> 3;
            int cg  = idx & 7;
            size_t g = (size_t)row * II + k0 + cg * 8;
            int s = row * LDP + cg * 8;
            *(uint4*)(Ah + s) = *(const uint4*)(gAh + g);
            *(uint4*)(Al + s) = *(const uint4*)(gAl + g);
            *(uint4*)(Bh + s) = *(const uint4*)(gBh + g);
            *(uint4*)(Bl + s) = *(const uint4*)(gBl + g);
        }
        __syncthreads();

#pragma unroll
        for (int kk = 0; kk < 4; kk++) {
            const int ks = kk * 16;
            uint32_t ah[2][4], al[2][4];
#pragma unroll
            for (int mi = 0; mi < 2; mi++) {
                ldsm4(ah[mi], smem_u32(Ah + (wm + mi * 16 + a_row) * LDP + ks + a_col));
                ldsm4(al[mi], smem_u32(Al + (wm + mi * 16 + a_row) * LDP + ks + a_col));
            }
#pragma unroll
            for (int g2 = 0; g2 < 4; g2++) {
                uint32_t bh4[4], bl4[4];
                ldsm4(bh4, smem_u32(Bh + (wn + g2 * 16 + b_row) * LDP + ks + b_col));
                ldsm4(bl4, smem_u32(Bl + (wn + g2 * 16 + b_row) * LDP + ks + b_col));
#pragma unroll
                for (int mi = 0; mi < 2; mi++) {
                    mma16816(acc[mi][g2 * 2],     ah[mi], bh4[0], bh4[1]);
                    mma16816(acc[mi][g2 * 2],     ah[mi], bl4[0], bl4[1]);
                    mma16816(acc[mi][g2 * 2],     al[mi], bh4[0], bh4[1]);
                    mma16816(acc[mi][g2 * 2 + 1], ah[mi], bh4[2], bh4[3]);
                    mma16816(acc[mi][g2 * 2 + 1], ah[mi], bl4[2], bl4[3]);
                    mma16816(acc[mi][g2 * 2 + 1], al[mi], bh4[2], bh4[3]);
                }
            }
        }
        __syncthreads();
    }

    const int colw = ntile * 128 + wn;
#pragma unroll
    for (int mi = 0; mi < 2; mi++) {
        int r0 = mtile * 128 + wm + mi * 16 + (lane >> 2);
#pragma unroll
        for (int nj = 0; nj < 8; nj++) {
            int c = colw + nj * 8 + (lane & 3) * 2;
            float b0 = bi[c] + bh[c];
            float b1 = bi[c + 1] + bh[c + 1];
            *(float2*)(outbuf + (size_t)r0 * GG + c) =
                make_float2(acc[mi][nj][0] + b0, acc[mi][nj][1] + b1);
            *(float2*)(outbuf + (size_t)(r0 + 8) * GG + c) =
                make_float2(acc[mi][nj][2] + b0, acc[mi][nj][3] + b1);
        }
    }
}

// ---------------------------------------------------------------------------
// Persistent tensor-core recurrence (v4): R11 structure (8 warps) + packed
// u64 h state (hi-pair | lo-pair) -> 4x LDG.64 per k-iter instead of
// 8x LDG.32, 100% sector efficiency (h L2 traffic halved), STG.64 publish.
// ---------------------------------------------------------------------------
#define LDKW 1032                        // padded row stride (bf16): 2064 B
#define RC_WH   (32 * LDKW * 2)          // one Wh buffer bytes (66048)
#define RC_RED  (6 * 32 * 16 * 4)        // 12288 B
#define RC_SMEM (2 * RC_WH + RC_RED)

__device__ __forceinline__ void grid_sync(unsigned& gen) {
    __syncthreads();
    if (threadIdx.x == 0) {
        __threadfence();
        unsigned arrived = atomicAdd(&g_bar_cnt, 1u);
        if (arrived == gridDim.x - 1) {
            g_bar_cnt = 0;
            __threadfence();
            g_bar_gen = gen + 1;
        } else {
            while (g_bar_gen <= gen) { }
            __threadfence();
        }
    }
    gen++;
    __syncthreads();
}

__global__ __launch_bounds__(256, 1) void lstm_persist_tc(
    const float* __restrict__ Wh, float* __restrict__ out)
{
    extern __shared__ char smem_raw[];
    __nv_bfloat16* WhHi = (__nv_bfloat16*)smem_raw;                 // [32][LDKW]
    __nv_bfloat16* WhLo = WhHi + 32 * LDKW;
    float* red = (float*)(smem_raw + 2 * RC_WH);                    // [6][32][16]

    const int bx    = blockIdx.x;
    const int tid   = threadIdx.x;
    const int w     = tid >> 5;
    const int lane  = tid & 31;
    const int mt    = w >> 2;        // 0..1 (m-tile of 16)
    const int kq    = w & 3;         // 0..3 (K quarter)
    const int hbase = bx * 8;

    // ---- one-time: load + split Wh slice into SMEM ----
    {
        const int n  = tid >> 3;         // 0..31
        const int cq = tid & 7;          // k chunk of 128
        const int grow = (n >> 3) * HH + hbase + (n & 7);
        const float* src = Wh + (size_t)grow * HH;
#pragma unroll 4
        for (int kk = 0; kk < 16; kk++) {
            int k = cq * 128 + kk * 8;
            float4 va = *(const float4*)(src + k);
            float4 vb = *(const float4*)(src + k + 4);
            float vv[8] = {va.x, va.y, va.z, va.w, vb.x, vb.y, vb.z, vb.w};
            __nv_bfloat16 h[8], l[8];
#pragma unroll
            for (int j = 0; j < 8; j++) split1(vv[j], h[j], l[j]);
            __nv_bfloat162* dh = (__nv_bfloat162*)(WhHi + n * LDKW + k);
            __nv_bfloat162* dl = (__nv_bfloat162*)(WhLo + n * LDKW + k);
#pragma unroll
            for (int j = 0; j < 4; j++) {
                dh[j] = __halves2bfloat162(h[2 * j], h[2 * j + 1]);
                dl[j] = __halves2bfloat162(l[2 * j], l[2 * j + 1]);
            }
        }
    }
    __syncthreads();

    const int b_row = ((lane >> 4) << 3) + (lane & 7);
    const int b_col = ((lane >> 3) & 1) << 3;
    const uint32_t bhi0_base = smem_u32(WhHi + b_row * LDKW + b_col);
    const uint32_t bhi1_base = smem_u32(WhHi + (16 + b_row) * LDKW + b_col);
    const uint32_t blo0_base = smem_u32(WhLo + b_row * LDKW + b_col);
    const uint32_t blo1_base = smem_u32(WhLo + (16 + b_row) * LDKW + b_col);

    // m16n8k16 lane map components
    const int ar0 = mt * 16 + (lane >> 2);       // batch rows ar0 and ar0+8
    const int ak  = (lane & 3) * 2;
    const int r0  = mt * 16 + (lane >> 2);       // output row (kq0 role)
    const int c0  = (lane & 3) * 2;              // output local col pair

    unsigned gen = 0;

    for (int t = 0; t < TT; t++) {
        const unsigned long long* hpk = g_hpk[t & 1];

        // ---- prefetch x_proj[t] gates + c (kq0 items) — overlaps K loop ----
        float xpr[4][4], cpr[4];
        if (kq == 0) {
            const float* xb = g_xproj + (size_t)t * BB * GG;
#pragma unroll
            for (int q = 0; q < 4; q++) {
                int b  = r0 + (q >> 1) * 8;
                int cc = c0 + (q & 1);
                const float* p = xb + (size_t)b * GG + hbase + cc;
                xpr[0][q] = p[0];
                xpr[1][q] = p[HH];
                xpr[2][q] = p[2 * HH];
                xpr[3][q] = p[3 * HH];
                cpr[q] = g_c[b * HH + hbase + cc];
            }
        }

        float acc[4][4];
#pragma unroll
        for (int f = 0; f < 4; f++)
#pragma unroll
            for (int q = 0; q < 4; q++) acc[f][q] = 0.f;

        // ---- K loop: this warp's quarter (256 K) ----
#pragma unroll 4
        for (int it = 0; it < 16; it++) {
            const int k = kq * 256 + it * 16;
            const int i00 = (ar0 * HH + k + ak) >> 1;
            const int i10 = ((ar0 + 8) * HH + k + ak) >> 1;
            unsigned long long v0 = hpk[i00];
            unsigned long long v1 = hpk[i10];
            unsigned long long v2 = hpk[i00 + 4];
            unsigned long long v3 = hpk[i10 + 4];
            uint32_t ah[4] = {(uint32_t)v0, (uint32_t)v1,
                              (uint32_t)v2, (uint32_t)v3};
            uint32_t al[4] = {(uint32_t)(v0 >> 32), (uint32_t)(v1 >> 32),
                              (uint32_t)(v2 >> 32), (uint32_t)(v3 >> 32)};

            uint32_t bh0[4], bh1[4], bl0[4], bl1[4];
            ldsm4(bh0, bhi0_base + k * 2);
            ldsm4(bh1, bhi1_base + k * 2);
            ldsm4(bl0, blo0_base + k * 2);
            ldsm4(bl1, blo1_base + k * 2);

            mma16816(acc[0], ah, bh0[0], bh0[1]);
            mma16816(acc[1], ah, bh0[2], bh0[3]);
            mma16816(acc[2], ah, bh1[0], bh1[1]);
            mma16816(acc[3], ah, bh1[2], bh1[3]);
            mma16816(acc[0], ah, bl0[0], bl0[1]);
            mma16816(acc[1], ah, bl0[2], bl0[3]);
            mma16816(acc[2], ah, bl1[0], bl1[1]);
            mma16816(acc[3], ah, bl1[2], bl1[3]);
            mma16816(acc[0], al, bh0[0], bh0[1]);
            mma16816(acc[1], al, bh0[2], bh0[3]);
            mma16816(acc[2], al, bh1[0], bh1[1]);
            mma16816(acc[3], al, bh1[2], bh1[3]);
        }

        // ---- cross-warp K reduction (fixed order -> deterministic) ----
        if (kq != 0) {
            float* rdst = red + ((mt * 3 + (kq - 1)) * 32 + lane) * 16;
#pragma unroll
            for (int f = 0; f < 4; f++)
#pragma unroll
                for (int q = 0; q < 4; q++) rdst[f * 4 + q] = acc[f][q];
        }
        __syncthreads();

        if (kq == 0) {
#pragma unroll
            for (int p = 0; p < 3; p++) {
                const float* rsrc = red + ((mt * 3 + p) * 32 + lane) * 16;
#pragma unroll
                for (int f = 0; f < 4; f++)
#pragma unroll
                    for (int q = 0; q < 4; q++) acc[f][q] += rsrc[f * 4 + q];
            }

            // ---- activations entirely in registers ----
            unsigned long long* hpk_n = g_hpk[(t + 1) & 1];
#pragma unroll
            for (int half = 0; half < 2; half++) {
                const int b = r0 + half * 8;
                float hn[2], cn[2];
#pragma unroll
                for (int j = 0; j < 2; j++) {
                    const int q = half * 2 + j;
                    float ig = sigmoidf_(acc[0][q] + xpr[0][q]);
                    float fg = sigmoidf_(acc[1][q] + xpr[1][q]);
                    float gg = tanhf(acc[2][q] + xpr[2][q]);
                    float og = sigmoidf_(acc[3][q] + xpr[3][q]);
                    cn[j] = fmaf(fg, cpr[q], ig * gg);
                    hn[j] = og * tanhf(cn[j]);
                }
                const int idx = b * HH + hbase + c0;
                *(float2*)(g_c + idx) = make_float2(cn[0], cn[1]);
                hpk_n[idx >> 1] = pack_h2(hn[0], hn[1]);
                *(float2*)(out + (size_t)b * TT * HH + (size_t)t * HH + hbase + c0) =
                    make_float2(hn[0], hn[1]);
            }
        }

        grid_sync(gen);   // h fully published before next step reads it
    }
}

// ---------------------------------------------------------------------------
// tail: h_T (= output[:, T-1, :]) and c_T appended after output [B,T,H]
// ---------------------------------------------------------------------------
__global__ void finish_kernel(float* __restrict__ out) {
    int i = blockIdx.x * blockDim.x + threadIdx.x;
    if (i < BB * HH) {
        int b = i >> 10, hc = i & (HH - 1);
        out[(size_t)BB * TT * HH + i] =
            out[(size_t)b * TT * HH + (size_t)(TT - 1) * HH + hc];
        out[(size_t)BB * TT * HH + BB * HH + i] = g_c[i];
    }
}

extern "C" void kernel_launch(void* const* d_in, const int* in_sizes, int n_in,
                              void* d_out, int out_size) {
    const float* x  = (const float*)d_in[0];
    const float* h0 = (const float*)d_in[1];
    const float* c0 = (const float*)d_in[2];
    const float* Wi = (const float*)d_in[3];
    const float* bi = (const float*)d_in[4];
    const float* Wh = (const float*)d_in[5];
    const float* bh = (const float*)d_in[6];
    float* out = (float*)d_out;

    cudaFuncSetAttribute(xproj_mma_kernel, cudaFuncAttributeMaxDynamicSharedMemorySize,
                         XP_SMEM);
    cudaFuncSetAttribute(lstm_persist_tc, cudaFuncAttributeMaxDynamicSharedMemorySize,
                         RC_SMEM);

    init_kernel<<<(BB * HH + 255) / 256, 256>>>(h0, c0);
    conv_x_kernel<<<4096, 256>>>(x);
    conv_w_kernel<<<1024, 256>>>(Wi);

    float* xproj_ptr;
    cudaGetSymbolAddress((void**)&xproj_ptr, g_xproj);
    xproj_mma_kernel<<<dim3(32, 128), 256, XP_SMEM>>>(bi, bh, xproj_ptr);

    lstm_persist_tc<<<128, 256, RC_SMEM>>>(Wh, out);
    finish_kernel<<<(BB * HH + 255) / 256, 256>>>(out);
}

// round 17
// speedup vs baseline: 1.2534x; 1.0444x over previous
#include <cuda_runtime.h>
#include <cuda_bf16.h>
#include <math.h>
#include <stdint.h>

#define BB 32
#define TT 512
#define II 1024
#define HH 1024
#define GG 4096   // 4*H

// ---- scratch (static __device__ arrays; no allocation allowed) ----
__device__ float g_xproj[67108864];            // [T][B][4H] (256 MB)
// packed hidden state: per hcol-pair, low u32 = bf16 hi-pair, high u32 = bf16 lo-pair
__device__ unsigned long long g_hpk[2][BB * HH / 2];
__device__ float g_c[BB * HH];
__device__ unsigned g_bar_cnt;                 // monotonic arrival counter
// bf16 hi/lo split operands for tensor-core xproj
__device__ __nv_bfloat16 g_xhi[TT * BB * II];  // [r=t*32+b][i]
__device__ __nv_bfloat16 g_xlo[TT * BB * II];
__device__ __nv_bfloat16 g_whi[GG * II];       // [n][k]
__device__ __nv_bfloat16 g_wlo[GG * II];

__device__ __forceinline__ float sigmoidf_(float x) {
    return 1.0f / (1.0f + __expf(-x));
}

__device__ __forceinline__ uint32_t smem_u32(const void* p) {
    uint32_t a;
    asm("{ .reg .u64 t; cvta.to.shared.u64 t, %1; cvt.u32.u64 %0, t; }"
        : "=r"(a) : "l"(p));
    return a;
}

// ldmatrix x4 (sm_75+)
__device__ __forceinline__ void ldsm4(uint32_t* r, uint32_t addr) {
    asm volatile("ldmatrix.sync.aligned.m8n8.x4.shared.b16 {%0,%1,%2,%3}, [%4];"
                 : "=r"(r[0]), "=r"(r[1]), "=r"(r[2]), "=r"(r[3]) : "r"(addr));
}
// mma.sync bf16 (sm_80+)
__device__ __forceinline__ void mma16816(float* c, const uint32_t* a,
                                         uint32_t b0, uint32_t b1) {
    asm volatile(
        "mma.sync.aligned.m16n8k16.row.col.f32.bf16.bf16.f32 "
        "{%0,%1,%2,%3}, {%4,%5,%6,%7}, {%8,%9}, {%0,%1,%2,%3};"
        : "+f"(c[0]), "+f"(c[1]), "+f"(c[2]), "+f"(c[3])
        : "r"(a[0]), "r"(a[1]), "r"(a[2]), "r"(a[3]), "r"(b0), "r"(b1));
}

// split a float into bf16 hi + bf16 lo
__device__ __forceinline__ void split1(float v, __nv_bfloat16& h, __nv_bfloat16& l) {
    h = __float2bfloat16(v);
    l = __float2bfloat16(v - __bfloat162float(h));
}

__device__ __forceinline__ uint32_t bf2_u32(__nv_bfloat16 a, __nv_bfloat16 b) {
    __nv_bfloat162 p = __halves2bfloat162(a, b);
    return *(uint32_t*)&p;
}

// pack two adjacent-hcol h values into one u64 (hi-pair low, lo-pair high)
__device__ __forceinline__ unsigned long long pack_h2(float v0, float v1) {
    __nv_bfloat16 h0, l0, h1, l1;
    split1(v0, h0, l0);
    split1(v1, h1, l1);
    return (unsigned long long)bf2_u32(h0, h1) |
           ((unsigned long long)bf2_u32(l0, l1) << 32);
}

// release arrive / acquire poll on the monotonic barrier counter
__device__ __forceinline__ void bar_arrive(unsigned* addr) {
    asm volatile("red.release.gpu.global.add.u32 [%0], %1;"
                 :: "l"(addr), "r"(1u) : "memory");
}
__device__ __forceinline__ unsigned bar_peek(unsigned* addr) {
    unsigned v;
    asm volatile("ld.acquire.gpu.global.u32 %0, [%1];"
                 : "=r"(v) : "l"(addr) : "memory");
    return v;
}

// ---------------------------------------------------------------------------
// init: c state, packed-split h0, barrier reset
// ---------------------------------------------------------------------------
__global__ void init_kernel(const float* __restrict__ h0, const float* __restrict__ c0) {
    int i = blockIdx.x * blockDim.x + threadIdx.x;
    if (i < BB * HH) g_c[i] = c0[i];
    if (i < BB * HH / 2)
        g_hpk[0][i] = pack_h2(h0[2 * i], h0[2 * i + 1]);
    if (i == 0) g_bar_cnt = 0;
}

__device__ __forceinline__ void split4(float4 v, __nv_bfloat16* hi, __nv_bfloat16* lo,
                                       size_t r) {
    float vv[4] = {v.x, v.y, v.z, v.w};
    __nv_bfloat16 h[4], l[4];
#pragma unroll
    for (int j = 0; j < 4; j++) split1(vv[j], h[j], l[j]);
    *(__nv_bfloat162*)(hi + r)     = __halves2bfloat162(h[0], h[1]);
    *(__nv_bfloat162*)(hi + r + 2) = __halves2bfloat162(h[2], h[3]);
    *(__nv_bfloat162*)(lo + r)     = __halves2bfloat162(l[0], l[1]);
    *(__nv_bfloat162*)(lo + r + 2) = __halves2bfloat162(l[2], l[3]);
}

__global__ void conv_x_kernel(const float* __restrict__ x) {
    int64_t n4 = (int64_t)TT * BB * II / 4;
    for (int64_t q = blockIdx.x * blockDim.x + threadIdx.x; q < n4;
         q += (int64_t)gridDim.x * blockDim.x) {
        int64_t i4 = q * 4;
        int i  = (int)(i4 & (II - 1));
        int bt = (int)(i4 >> 10);
        int t  = bt & (TT - 1);
        int b  = bt >> 9;
        float4 v = *(const float4*)(x + i4);
        size_t r = ((size_t)t * BB + b) * II + i;
        split4(v, g_xhi, g_xlo, r);
    }
}

__global__ void conv_w_kernel(const float* __restrict__ Wi) {
    int64_t n4 = (int64_t)GG * II / 4;
    for (int64_t q = blockIdx.x * blockDim.x + threadIdx.x; q < n4;
         q += (int64_t)gridDim.x * blockDim.x) {
        float4 v = *(const float4*)(Wi + q * 4);
        split4(v, g_whi, g_wlo, (size_t)q * 4);
    }
}

// ---------------------------------------------------------------------------
// xproj GEMM via mma.sync bf16 (validated R8 version, unchanged).
// ---------------------------------------------------------------------------
#define LDP 72
#define XP_SMEM (4 * 128 * LDP * 2)

__global__ __launch_bounds__(256, 2) void xproj_mma_kernel(
    const float* __restrict__ bi, const float* __restrict__ bh,
    float* __restrict__ outbuf)
{
    extern __shared__ char smem[];
    __nv_bfloat16* Ah = (__nv_bfloat16*)smem;
    __nv_bfloat16* Al = Ah + 128 * LDP;
    __nv_bfloat16* Bh = Al + 128 * LDP;
    __nv_bfloat16* Bl = Bh + 128 * LDP;

    const int tid  = threadIdx.x;
    const int w    = tid >> 5;
    const int lane = tid & 31;
    const int ntile = blockIdx.x;
    const int mtile = blockIdx.y;
    const int wm = (w >> 1) * 32;
    const int wn = (w & 1) * 64;

    const __nv_bfloat16* gAh = g_xhi + (size_t)(mtile * 128) * II;
    const __nv_bfloat16* gAl = g_xlo + (size_t)(mtile * 128) * II;
    const __nv_bfloat16* gBh = g_whi + (size_t)(ntile * 128) * II;
    const __nv_bfloat16* gBl = g_wlo + (size_t)(ntile * 128) * II;

    float acc[2][8][4];
#pragma unroll
    for (int mi = 0; mi < 2; mi++)
#pragma unroll
        for (int nj = 0; nj < 8; nj++)
#pragma unroll
            for (int q = 0; q < 4; q++) acc[mi][nj][q] = 0.f;

    const int a_row = lane & 15;
    const int a_col = (lane >> 4) << 3;
    const int b_row = ((lane >> 4) << 3) + (lane & 7);
    const int b_col = ((lane >> 3) & 1) << 3;

    for (int chunk = 0; chunk < 16; chunk++) {
        const int k0 = chunk * 64;
#pragma unroll
        for (int it = 0; it < 4; it++) {
            int idx = tid + it * 256;
            int row = idx >> 3;
            int cg  = idx & 7;
            size_t g = (size_t)row * II + k0 + cg * 8;
            int s = row * LDP + cg * 8;
            *(uint4*)(Ah + s) = *(const uint4*)(gAh + g);
            *(uint4*)(Al + s) = *(const uint4*)(gAl + g);
            *(uint4*)(Bh + s) = *(const uint4*)(gBh + g);
            *(uint4*)(Bl + s) = *(const uint4*)(gBl + g);
        }
        __syncthreads();

#pragma unroll
        for (int kk = 0; kk < 4; kk++) {
            const int ks = kk * 16;
            uint32_t ah[2][4], al[2][4];
#pragma unroll
            for (int mi = 0; mi < 2; mi++) {
                ldsm4(ah[mi], smem_u32(Ah + (wm + mi * 16 + a_row) * LDP + ks + a_col));
                ldsm4(al[mi], smem_u32(Al + (wm + mi * 16 + a_row) * LDP + ks + a_col));
            }
#pragma unroll
            for (int g2 = 0; g2 < 4; g2++) {
                uint32_t bh4[4], bl4[4];
                ldsm4(bh4, smem_u32(Bh + (wn + g2 * 16 + b_row) * LDP + ks + b_col));
                ldsm4(bl4, smem_u32(Bl + (wn + g2 * 16 + b_row) * LDP + ks + b_col));
#pragma unroll
                for (int mi = 0; mi < 2; mi++) {
                    mma16816(acc[mi][g2 * 2],     ah[mi], bh4[0], bh4[1]);
                    mma16816(acc[mi][g2 * 2],     ah[mi], bl4[0], bl4[1]);
                    mma16816(acc[mi][g2 * 2],     al[mi], bh4[0], bh4[1]);
                    mma16816(acc[mi][g2 * 2 + 1], ah[mi], bh4[2], bh4[3]);
                    mma16816(acc[mi][g2 * 2 + 1], ah[mi], bl4[2], bl4[3]);
                    mma16816(acc[mi][g2 * 2 + 1], al[mi], bh4[2], bh4[3]);
                }
            }
        }
        __syncthreads();
    }

    const int colw = ntile * 128 + wn;
#pragma unroll
    for (int mi = 0; mi < 2; mi++) {
        int r0 = mtile * 128 + wm + mi * 16 + (lane >> 2);
#pragma unroll
        for (int nj = 0; nj < 8; nj++) {
            int c = colw + nj * 8 + (lane & 3) * 2;
            float b0 = bi[c] + bh[c];
            float b1 = bi[c + 1] + bh[c + 1];
            *(float2*)(outbuf + (size_t)r0 * GG + c) =
                make_float2(acc[mi][nj][0] + b0, acc[mi][nj][1] + b1);
            *(float2*)(outbuf + (size_t)(r0 + 8) * GG + c) =
                make_float2(acc[mi][nj][2] + b0, acc[mi][nj][3] + b1);
        }
    }
}

// ---------------------------------------------------------------------------
// Persistent tensor-core recurrence (v5): packed u64 h state (R15, proven) +
//  - monotonic-counter barrier: kq0 warps release-arrive right after their
//    STG; all warps acquire-poll; NO syncthreads in the barrier at all.
//    (Safe: kq0 arrives only after consuming `red`; kq!=0 rewrite `red` only
//    after the barrier opens, which requires kq0's arrival.)
//  - c carried in registers across all 512 steps (writer == next reader);
//    g_c written once at t=TT-1 for finish_kernel.
//  - x_proj[t+1] prefetch issued before the barrier poll (overlaps wait).
// ---------------------------------------------------------------------------
#define LDKW 1032                        // padded row stride (bf16): 2064 B
#define RC_WH   (32 * LDKW * 2)          // one Wh buffer bytes (66048)
#define RC_RED  (6 * 32 * 16 * 4)        // 12288 B
#define RC_SMEM (2 * RC_WH + RC_RED)

__global__ __launch_bounds__(256, 1) void lstm_persist_tc(
    const float* __restrict__ Wh, float* __restrict__ out)
{
    extern __shared__ char smem_raw[];
    __nv_bfloat16* WhHi = (__nv_bfloat16*)smem_raw;                 // [32][LDKW]
    __nv_bfloat16* WhLo = WhHi + 32 * LDKW;
    float* red = (float*)(smem_raw + 2 * RC_WH);                    // [6][32][16]

    const int bx    = blockIdx.x;
    const int tid   = threadIdx.x;
    const int w     = tid >> 5;
    const int lane  = tid & 31;
    const int mt    = w >> 2;        // 0..1 (m-tile of 16)
    const int kq    = w & 3;         // 0..3 (K quarter)
    const int hbase = bx * 8;

    // ---- one-time: load + split Wh slice into SMEM ----
    {
        const int n  = tid >> 3;         // 0..31
        const int cq = tid & 7;          // k chunk of 128
        const int grow = (n >> 3) * HH + hbase + (n & 7);
        const float* src = Wh + (size_t)grow * HH;
#pragma unroll 4
        for (int kk = 0; kk < 16; kk++) {
            int k = cq * 128 + kk * 8;
            float4 va = *(const float4*)(src + k);
            float4 vb = *(const float4*)(src + k + 4);
            float vv[8] = {va.x, va.y, va.z, va.w, vb.x, vb.y, vb.z, vb.w};
            __nv_bfloat16 h[8], l[8];
#pragma unroll
            for (int j = 0; j < 8; j++) split1(vv[j], h[j], l[j]);
            __nv_bfloat162* dh = (__nv_bfloat162*)(WhHi + n * LDKW + k);
            __nv_bfloat162* dl = (__nv_bfloat162*)(WhLo + n * LDKW + k);
#pragma unroll
            for (int j = 0; j < 4; j++) {
                dh[j] = __halves2bfloat162(h[2 * j], h[2 * j + 1]);
                dl[j] = __halves2bfloat162(l[2 * j], l[2 * j + 1]);
            }
        }
    }
    __syncthreads();

    const int b_row = ((lane >> 4) << 3) + (lane & 7);
    const int b_col = ((lane >> 3) & 1) << 3;
    const uint32_t bhi0_base = smem_u32(WhHi + b_row * LDKW + b_col);
    const uint32_t bhi1_base = smem_u32(WhHi + (16 + b_row) * LDKW + b_col);
    const uint32_t blo0_base = smem_u32(WhLo + b_row * LDKW + b_col);
    const uint32_t blo1_base = smem_u32(WhLo + (16 + b_row) * LDKW + b_col);

    // m16n8k16 lane map components
    const int ar0 = mt * 16 + (lane >> 2);       // batch rows ar0 and ar0+8
    const int ak  = (lane & 3) * 2;
    const int r0  = mt * 16 + (lane >> 2);       // output row (kq0 role)
    const int c0  = (lane & 3) * 2;              // output local col pair

    // ---- kq0 register state: c and x_proj prefetch ----
    float xpr[4][4], creg[4];
    if (kq == 0) {
#pragma unroll
        for (int q = 0; q < 4; q++) {
            int b  = r0 + (q >> 1) * 8;
            int cc = c0 + (q & 1);
            creg[q] = g_c[b * HH + hbase + cc];
            const float* p = g_xproj + (size_t)b * GG + hbase + cc;  // t = 0
            xpr[0][q] = p[0];
            xpr[1][q] = p[HH];
            xpr[2][q] = p[2 * HH];
            xpr[3][q] = p[3 * HH];
        }
    }

    unsigned target = 0;

    for (int t = 0; t < TT; t++) {
        const unsigned long long* hpk = g_hpk[t & 1];

        float acc[4][4];
#pragma unroll
        for (int f = 0; f < 4; f++)
#pragma unroll
            for (int q = 0; q < 4; q++) acc[f][q] = 0.f;

        // ---- K loop: this warp's quarter (256 K) ----
#pragma unroll 4
        for (int it = 0; it < 16; it++) {
            const int k = kq * 256 + it * 16;
            const int i00 = (ar0 * HH + k + ak) >> 1;
            const int i10 = ((ar0 + 8) * HH + k + ak) >> 1;
            unsigned long long v0 = hpk[i00];
            unsigned long long v1 = hpk[i10];
            unsigned long long v2 = hpk[i00 + 4];
            unsigned long long v3 = hpk[i10 + 4];
            uint32_t ah[4] = {(uint32_t)v0, (uint32_t)v1,
                              (uint32_t)v2, (uint32_t)v3};
            uint32_t al[4] = {(uint32_t)(v0 >> 32), (uint32_t)(v1 >> 32),
                              (uint32_t)(v2 >> 32), (uint32_t)(v3 >> 32)};

            uint32_t bh0[4], bh1[4], bl0[4], bl1[4];
            ldsm4(bh0, bhi0_base + k * 2);
            ldsm4(bh1, bhi1_base + k * 2);
            ldsm4(bl0, blo0_base + k * 2);
            ldsm4(bl1, blo1_base + k * 2);

            mma16816(acc[0], ah, bh0[0], bh0[1]);
            mma16816(acc[1], ah, bh0[2], bh0[3]);
            mma16816(acc[2], ah, bh1[0], bh1[1]);
            mma16816(acc[3], ah, bh1[2], bh1[3]);
            mma16816(acc[0], ah, bl0[0], bl0[1]);
            mma16816(acc[1], ah, bl0[2], bl0[3]);
            mma16816(acc[2], ah, bl1[0], bl1[1]);
            mma16816(acc[3], ah, bl1[2], bl1[3]);
            mma16816(acc[0], al, bh0[0], bh0[1]);
            mma16816(acc[1], al, bh0[2], bh0[3]);
            mma16816(acc[2], al, bh1[0], bh1[1]);
            mma16816(acc[3], al, bh1[2], bh1[3]);
        }

        // ---- cross-warp K reduction (fixed order -> deterministic) ----
        if (kq != 0) {
            float* rdst = red + ((mt * 3 + (kq - 1)) * 32 + lane) * 16;
#pragma unroll
            for (int f = 0; f < 4; f++)
#pragma unroll
                for (int q = 0; q < 4; q++) rdst[f * 4 + q] = acc[f][q];
        }
        __syncthreads();

        if (kq == 0) {
#pragma unroll
            for (int p = 0; p < 3; p++) {
                const float* rsrc = red + ((mt * 3 + p) * 32 + lane) * 16;
#pragma unroll
                for (int f = 0; f < 4; f++)
#pragma unroll
                    for (int q = 0; q < 4; q++) acc[f][q] += rsrc[f * 4 + q];
            }

            // ---- activations entirely in registers; c stays in registers ----
            unsigned long long* hpk_n = g_hpk[(t + 1) & 1];
#pragma unroll
            for (int half = 0; half < 2; half++) {
                const int b = r0 + half * 8;
                float hn[2];
#pragma unroll
                for (int j = 0; j < 2; j++) {
                    const int q = half * 2 + j;
                    float ig = sigmoidf_(acc[0][q] + xpr[0][q]);
                    float fg = sigmoidf_(acc[1][q] + xpr[1][q]);
                    float gg = tanhf(acc[2][q] + xpr[2][q]);
                    float og = sigmoidf_(acc[3][q] + xpr[3][q]);
                    float cn = fmaf(fg, creg[q], ig * gg);
                    creg[q] = cn;
                    hn[j] = og * tanhf(cn);
                }
                const int idx = b * HH + hbase + c0;
                hpk_n[idx >> 1] = pack_h2(hn[0], hn[1]);
                *(float2*)(out + (size_t)b * TT * HH + (size_t)t * HH + hbase + c0) =
                    make_float2(hn[0], hn[1]);
                if (t == TT - 1)
                    *(float2*)(g_c + idx) = make_float2(creg[half * 2], creg[half * 2 + 1]);
            }

            // ---- release-arrive (covers the STGs above), then prefetch t+1 ----
            if (lane == 0) bar_arrive(&g_bar_cnt);
            if (t + 1 < TT) {
                const float* xb = g_xproj + (size_t)(t + 1) * BB * GG;
#pragma unroll
                for (int q = 0; q < 4; q++) {
                    int b  = r0 + (q >> 1) * 8;
                    int cc = c0 + (q & 1);
                    const float* p = xb + (size_t)b * GG + hbase + cc;
                    xpr[0][q] = p[0];
                    xpr[1][q] = p[HH];
                    xpr[2][q] = p[2 * HH];
                    xpr[3][q] = p[3 * HH];
                }
            }
        }

        // ---- acquire-poll: proceed when all 256 kq0-warp arrivals landed ----
        target += 256;
        while (bar_peek(&g_bar_cnt) < target) { }
        __syncwarp();
    }
}

// ---------------------------------------------------------------------------
// tail: h_T (= output[:, T-1, :]) and c_T appended after output [B,T,H]
// ---------------------------------------------------------------------------
__global__ void finish_kernel(float* __restrict__ out) {
    int i = blockIdx.x * blockDim.x + threadIdx.x;
    if (i < BB * HH) {
        int b = i >> 10, hc = i & (HH - 1);
        out[(size_t)BB * TT * HH + i] =
            out[(size_t)b * TT * HH + (size_t)(TT - 1) * HH + hc];
        out[(size_t)BB * TT * HH + BB * HH + i] = g_c[i];
    }
}

extern "C" void kernel_launch(void* const* d_in, const int* in_sizes, int n_in,
                              void* d_out, int out_size) {
    const float* x  = (const float*)d_in[0];
    const float* h0 = (const float*)d_in[1];
    const float* c0 = (const float*)d_in[2];
    const float* Wi = (const float*)d_in[3];
    const float* bi = (const float*)d_in[4];
    const float* Wh = (const float*)d_in[5];
    const float* bh = (const float*)d_in[6];
    float* out = (float*)d_out;

    cudaFuncSetAttribute(xproj_mma_kernel, cudaFuncAttributeMaxDynamicSharedMemorySize,
                         XP_SMEM);
    cudaFuncSetAttribute(lstm_persist_tc, cudaFuncAttributeMaxDynamicSharedMemorySize,
                         RC_SMEM);

    init_kernel<<<(BB * HH + 255) / 256, 256>>>(h0, c0);
    conv_x_kernel<<<4096, 256>>>(x);
    conv_w_kernel<<<1024, 256>>>(Wi);

    float* xproj_ptr;
    cudaGetSymbolAddress((void**)&xproj_ptr, g_xproj);
    xproj_mma_kernel<<<dim3(32, 128), 256, XP_SMEM>>>(bi, bh, xproj_ptr);

    lstm_persist_tc<<<128, 256, RC_SMEM>>>(Wh, out);
    finish_kernel<<<(BB * HH + 255) / 256, 256>>>(out);
}